// round 14
// baseline (speedup 1.0000x reference)
#include <cuda_runtime.h>
#include <cstdint>

// Problem constants (fixed by setup_inputs: N=64, T=400, D=1024, M=256)
#define NTOK 25600
#define DDIM 1024
#define MCOD 256
#define ROWS_PER_BLK 64
#define KC 16
#define XLD 68        // padded row stride for xs tile (bank-conflict mitigation)
#define P1_BLOCKS 296 // phase-1: 296 x 64 rows = 18944 rows (exactly 2 tiles/SM)
#define P1_ROWS (P1_BLOCKS * ROWS_PER_BLK)
#define TROWS2 16     // phase-2 tile rows
#define P2_BLOCKS ((NTOK - P1_ROWS) / TROWS2)   // 416 x 16 = 6656 rows

// ---------------- device scratch (allocation-free per harness rules) ----------------
__device__ float  g_enorm[MCOD * DDIM];
__device__ float  g_se[MCOD];
__device__ int    g_counts[MCOD];
__device__ double g_loss;

// ---------------------------------------------------------------------------
// emb_norm[m] = emb[m] / (||emb[m]|| + 1e-4);  se[m] = sum(emb_norm[m]^2)
// Replicates reference rounding: fp32 sum -> sqrtf (IEEE) -> +1e-4 -> IEEE div
// Block 0 additionally zeroes the cross-launch accumulators (graph replays).
// ---------------------------------------------------------------------------
__global__ __launch_bounds__(256) void vq_normalize(const float* __restrict__ emb) {
    __shared__ float red[256];
    const int m = blockIdx.x;
    const int t = threadIdx.x;

    if (m == 0) {             // fold vq_init: counts/loss reset before vq_main
        g_counts[t] = 0;
        if (t == 0) g_loss = 0.0;
    }

    float4 v = ((const float4*)(emb + (size_t)m * DDIM))[t];
    red[t] = v.x * v.x + v.y * v.y + v.z * v.z + v.w * v.w;
    __syncthreads();
    for (int s = 128; s > 0; s >>= 1) {
        if (t < s) red[t] += red[t + s];
        __syncthreads();
    }
    float denom = __fadd_rn(sqrtf(red[0]), 1e-4f);
    __syncthreads();

    float4 e;
    e.x = __fdiv_rn(v.x, denom);
    e.y = __fdiv_rn(v.y, denom);
    e.z = __fdiv_rn(v.z, denom);
    e.w = __fdiv_rn(v.w, denom);
    ((float4*)(g_enorm + (size_t)m * DDIM))[t] = e;

    red[t] = e.x * e.x + e.y * e.y + e.z * e.z + e.w * e.w;
    __syncthreads();
    for (int s = 128; s > 0; s >>= 1) {
        if (t < s) red[t] += red[t + s];
        __syncthreads();
    }
    if (t == 0) g_se[m] = red[0];
}

// ---------------------------------------------------------------------------
// Phase 1: 64-row tiles (identical math to the round-12 kernel).
// 256 threads = 16 ty (row groups of 4) x 16 tx2 (code groups of 16).
// ---------------------------------------------------------------------------
__global__ __launch_bounds__(256, 2) void vq_main(const float* __restrict__ x,
                                                  const float* __restrict__ emb,
                                                  float* __restrict__ out) {
    __shared__ __align__(16) float xs[KC][XLD];
    __shared__ __align__(16) float es[KC][MCOD];
    __shared__ float ssx[ROWS_PER_BLK];
    __shared__ int   sidx[ROWS_PER_BLK];
    __shared__ float sred[256];

    const int t   = threadIdx.x;
    const int ty  = t >> 4;
    const int tx2 = t & 15;
    const size_t rowBase = (size_t)blockIdx.x * ROWS_PER_BLK;

    float acc[4][16];
#pragma unroll
    for (int i = 0; i < 4; i++)
#pragma unroll
        for (int j = 0; j < 16; j++) acc[i][j] = 0.f;

    const int lr = t >> 2;
    const int lq = t & 3;
    const float* xld = x + (rowBase + lr) * DDIM + lq * 4;
    const float* eld = g_enorm + (size_t)t * DDIM;
    float sxp = 0.f;

    for (int k0 = 0; k0 < DDIM; k0 += KC) {
        float4 xv = *(const float4*)(xld + k0);
        sxp = __fmaf_rn(xv.x, xv.x, sxp);
        sxp = __fmaf_rn(xv.y, xv.y, sxp);
        sxp = __fmaf_rn(xv.z, xv.z, sxp);
        sxp = __fmaf_rn(xv.w, xv.w, sxp);
        xs[lq * 4 + 0][lr] = xv.x;
        xs[lq * 4 + 1][lr] = xv.y;
        xs[lq * 4 + 2][lr] = xv.z;
        xs[lq * 4 + 3][lr] = xv.w;
#pragma unroll
        for (int q = 0; q < 4; q++) {
            float4 ev = *(const float4*)(eld + k0 + q * 4);
            es[q * 4 + 0][t] = ev.x;
            es[q * 4 + 1][t] = ev.y;
            es[q * 4 + 2][t] = ev.z;
            es[q * 4 + 3][t] = ev.w;
        }
        __syncthreads();

#pragma unroll
        for (int k = 0; k < KC; k++) {
            float4 xr4 = *(const float4*)&xs[k][ty * 4];
            float xr[4] = {xr4.x, xr4.y, xr4.z, xr4.w};
#pragma unroll
            for (int g = 0; g < 4; g++) {
                float4 er4 = *(const float4*)&es[k][g * 64 + tx2 * 4];
                float er[4] = {er4.x, er4.y, er4.z, er4.w};
#pragma unroll
                for (int i = 0; i < 4; i++)
#pragma unroll
                    for (int j = 0; j < 4; j++)
                        acc[i][g * 4 + j] = __fmaf_rn(xr[i], er[j], acc[i][g * 4 + j]);
            }
        }
        __syncthreads();
    }

    sxp += __shfl_xor_sync(0xffffffffu, sxp, 1);
    sxp += __shfl_xor_sync(0xffffffffu, sxp, 2);
    if (lq == 0) ssx[lr] = sxp;
    __syncthreads();

    const float sx[4] = {ssx[ty * 4 + 0], ssx[ty * 4 + 1],
                         ssx[ty * 4 + 2], ssx[ty * 4 + 3]};

    float bestD[4] = {3.4e38f, 3.4e38f, 3.4e38f, 3.4e38f};
    int   bestI[4] = {0, 0, 0, 0};
#pragma unroll
    for (int g = 0; g < 4; g++) {
#pragma unroll
        for (int j = 0; j < 4; j++) {
            const int cod = g * 64 + tx2 * 4 + j;
            const float sev = g_se[cod];
#pragma unroll
            for (int i = 0; i < 4; i++) {
                float d = __fsub_rn(__fadd_rn(sev, sx[i]),
                                    __fmul_rn(2.0f, acc[i][g * 4 + j]));
                if (d < bestD[i] || (d == bestD[i] && cod < bestI[i])) {
                    bestD[i] = d;
                    bestI[i] = cod;
                }
            }
        }
    }

#pragma unroll
    for (int i = 0; i < 4; i++) {
        float d = bestD[i];
        int   bi = bestI[i];
        for (int off = 8; off > 0; off >>= 1) {
            float od = __shfl_down_sync(0xffffffffu, d, off, 16);
            int   oi = __shfl_down_sync(0xffffffffu, bi, off, 16);
            if (od < d || (od == d && oi < bi)) { d = od; bi = oi; }
        }
        if (tx2 == 0) sidx[ty * 4 + i] = bi;
    }
    __syncthreads();

    if (t < ROWS_PER_BLK) atomicAdd(&g_counts[sidx[t]], 1);

    float lloss = 0.f;
    for (int r = 0; r < ROWS_PER_BLK; ++r) {
        const int idx = sidx[r];
        float4 q  = ((const float4*)(emb + (size_t)idx * DDIM))[t];
        float4 xv = ((const float4*)(x + (rowBase + r) * DDIM))[t];
        float4 o;
        {
            float st = __fadd_rn(xv.x, __fsub_rn(q.x, xv.x));
            o.x = __fmul_rn(__fadd_rn(st, q.x), 0.5f);
            float dd = __fsub_rn(xv.x, q.x);
            lloss = __fmaf_rn(dd, dd, lloss);
        }
        {
            float st = __fadd_rn(xv.y, __fsub_rn(q.y, xv.y));
            o.y = __fmul_rn(__fadd_rn(st, q.y), 0.5f);
            float dd = __fsub_rn(xv.y, q.y);
            lloss = __fmaf_rn(dd, dd, lloss);
        }
        {
            float st = __fadd_rn(xv.z, __fsub_rn(q.z, xv.z));
            o.z = __fmul_rn(__fadd_rn(st, q.z), 0.5f);
            float dd = __fsub_rn(xv.z, q.z);
            lloss = __fmaf_rn(dd, dd, lloss);
        }
        {
            float st = __fadd_rn(xv.w, __fsub_rn(q.w, xv.w));
            o.w = __fmul_rn(__fadd_rn(st, q.w), 0.5f);
            float dd = __fsub_rn(xv.w, q.w);
            lloss = __fmaf_rn(dd, dd, lloss);
        }
        ((float4*)out)[(rowBase + r) * (DDIM / 4) + t] = o;
    }

    sred[t] = lloss;
    __syncthreads();
    for (int s = 128; s > 0; s >>= 1) {
        if (t < s) sred[t] += sred[t + s];
        __syncthreads();
    }
    if (t == 0) atomicAdd(&g_loss, (double)sred[0]);
}

// ---------------------------------------------------------------------------
// Phase 2: 16-row tail tiles (rows P1_ROWS..NTOK-1).  128 threads = 8 ty
// (row pairs) x 16 tx2; thread tile 2 rows x 16 codes.  Same k-ascending FMA
// chain, same argmin rounding/tiebreak, same gather arithmetic -> distances
// and output bitwise identical to the 64-row kernel.
// ---------------------------------------------------------------------------
__global__ __launch_bounds__(128, 4) void vq_main_tail(const float* __restrict__ x,
                                                       const float* __restrict__ emb,
                                                       float* __restrict__ out) {
    __shared__ __align__(16) float xs[KC][TROWS2 + 2];
    __shared__ __align__(16) float es[KC][MCOD];
    __shared__ float ssx[TROWS2];
    __shared__ int   sidx[TROWS2];
    __shared__ float sred[128];

    const int t   = threadIdx.x;
    const int ty  = t >> 4;          // 0..7
    const int tx2 = t & 15;
    const size_t rowBase = (size_t)P1_ROWS + (size_t)blockIdx.x * TROWS2;

    float acc[2][16];
#pragma unroll
    for (int i = 0; i < 2; i++)
#pragma unroll
        for (int j = 0; j < 16; j++) acc[i][j] = 0.f;

    // x tile: threads 0..63 load one float4 (row lr, quad lq)
    const int lr = t >> 2;           // 0..31 (valid < 16)
    const int lq = t & 3;
    const float* xld = x + (rowBase + (lr & 15)) * DDIM + lq * 4;
    // e tile: thread loads codes t and t+128
    const float* eld0 = g_enorm + (size_t)t * DDIM;
    const float* eld1 = g_enorm + (size_t)(t + 128) * DDIM;
    float sxp = 0.f;

    for (int k0 = 0; k0 < DDIM; k0 += KC) {
        if (t < 64) {
            float4 xv = *(const float4*)(xld + k0);
            sxp = __fmaf_rn(xv.x, xv.x, sxp);
            sxp = __fmaf_rn(xv.y, xv.y, sxp);
            sxp = __fmaf_rn(xv.z, xv.z, sxp);
            sxp = __fmaf_rn(xv.w, xv.w, sxp);
            xs[lq * 4 + 0][lr] = xv.x;
            xs[lq * 4 + 1][lr] = xv.y;
            xs[lq * 4 + 2][lr] = xv.z;
            xs[lq * 4 + 3][lr] = xv.w;
        }
#pragma unroll
        for (int q = 0; q < 4; q++) {
            float4 e0 = *(const float4*)(eld0 + k0 + q * 4);
            es[q * 4 + 0][t] = e0.x;
            es[q * 4 + 1][t] = e0.y;
            es[q * 4 + 2][t] = e0.z;
            es[q * 4 + 3][t] = e0.w;
            float4 e1 = *(const float4*)(eld1 + k0 + q * 4);
            es[q * 4 + 0][t + 128] = e1.x;
            es[q * 4 + 1][t + 128] = e1.y;
            es[q * 4 + 2][t + 128] = e1.z;
            es[q * 4 + 3][t + 128] = e1.w;
        }
        __syncthreads();

#pragma unroll
        for (int k = 0; k < KC; k++) {
            float x0 = xs[k][2 * ty];
            float x1 = xs[k][2 * ty + 1];
#pragma unroll
            for (int g = 0; g < 4; g++) {
                float4 er4 = *(const float4*)&es[k][g * 64 + tx2 * 4];
                float er[4] = {er4.x, er4.y, er4.z, er4.w};
#pragma unroll
                for (int j = 0; j < 4; j++) {
                    acc[0][g * 4 + j] = __fmaf_rn(x0, er[j], acc[0][g * 4 + j]);
                    acc[1][g * 4 + j] = __fmaf_rn(x1, er[j], acc[1][g * 4 + j]);
                }
            }
        }
        __syncthreads();
    }

    if (t < 64) {
        sxp += __shfl_xor_sync(0xffffffffu, sxp, 1);
        sxp += __shfl_xor_sync(0xffffffffu, sxp, 2);
        if (lq == 0) ssx[lr] = sxp;
    }
    __syncthreads();

    const float sx[2] = {ssx[2 * ty], ssx[2 * ty + 1]};

    float bestD[2] = {3.4e38f, 3.4e38f};
    int   bestI[2] = {0, 0};
#pragma unroll
    for (int g = 0; g < 4; g++) {
#pragma unroll
        for (int j = 0; j < 4; j++) {
            const int cod = g * 64 + tx2 * 4 + j;
            const float sev = g_se[cod];
#pragma unroll
            for (int i = 0; i < 2; i++) {
                float d = __fsub_rn(__fadd_rn(sev, sx[i]),
                                    __fmul_rn(2.0f, acc[i][g * 4 + j]));
                if (d < bestD[i] || (d == bestD[i] && cod < bestI[i])) {
                    bestD[i] = d;
                    bestI[i] = cod;
                }
            }
        }
    }

#pragma unroll
    for (int i = 0; i < 2; i++) {
        float d = bestD[i];
        int   bi = bestI[i];
        for (int off = 8; off > 0; off >>= 1) {
            float od = __shfl_down_sync(0xffffffffu, d, off, 16);
            int   oi = __shfl_down_sync(0xffffffffu, bi, off, 16);
            if (od < d || (od == d && oi < bi)) { d = od; bi = oi; }
        }
        if (tx2 == 0) sidx[2 * ty + i] = bi;
    }
    __syncthreads();

    if (t < TROWS2) atomicAdd(&g_counts[sidx[t]], 1);

    // gather: each thread handles float4 positions t and t+128 per row
    float lloss = 0.f;
    for (int r = 0; r < TROWS2; ++r) {
        const int idx = sidx[r];
        const float4* qp = (const float4*)(emb + (size_t)idx * DDIM);
        const float4* xp = (const float4*)(x + (rowBase + r) * DDIM);
        float4* op = (float4*)out + (rowBase + r) * (DDIM / 4);
#pragma unroll
        for (int h = 0; h < 2; h++) {
            const int p = t + h * 128;
            float4 q  = qp[p];
            float4 xv = xp[p];
            float4 o;
            {
                float st = __fadd_rn(xv.x, __fsub_rn(q.x, xv.x));
                o.x = __fmul_rn(__fadd_rn(st, q.x), 0.5f);
                float dd = __fsub_rn(xv.x, q.x);
                lloss = __fmaf_rn(dd, dd, lloss);
            }
            {
                float st = __fadd_rn(xv.y, __fsub_rn(q.y, xv.y));
                o.y = __fmul_rn(__fadd_rn(st, q.y), 0.5f);
                float dd = __fsub_rn(xv.y, q.y);
                lloss = __fmaf_rn(dd, dd, lloss);
            }
            {
                float st = __fadd_rn(xv.z, __fsub_rn(q.z, xv.z));
                o.z = __fmul_rn(__fadd_rn(st, q.z), 0.5f);
                float dd = __fsub_rn(xv.z, q.z);
                lloss = __fmaf_rn(dd, dd, lloss);
            }
            {
                float st = __fadd_rn(xv.w, __fsub_rn(q.w, xv.w));
                o.w = __fmul_rn(__fadd_rn(st, q.w), 0.5f);
                float dd = __fsub_rn(xv.w, q.w);
                lloss = __fmaf_rn(dd, dd, lloss);
            }
            op[p] = o;
        }
    }

    sred[t] = lloss;
    __syncthreads();
    for (int s = 64; s > 0; s >>= 1) {
        if (t < s) sred[t] += sred[t + s];
        __syncthreads();
    }
    if (t == 0) atomicAdd(&g_loss, (double)sred[0]);
}

// ---------------------------------------------------------------------------
// Scalars: commitment_loss = mean((x-q)^2), perplexity = exp(-sum p log(p+1e-10))
// ---------------------------------------------------------------------------
__global__ void vq_finalize(float* __restrict__ out) {
    __shared__ float red[256];
    const int t = threadIdx.x;
    float p = (float)g_counts[t] / 25600.0f;
    float term = __fmul_rn(p, logf(__fadd_rn(p, 1e-10f)));
    red[t] = term;
    __syncthreads();
    for (int s = 128; s > 0; s >>= 1) {
        if (t < s) red[t] += red[t + s];
        __syncthreads();
    }
    if (t == 0) {
        out[26214400] = (float)(g_loss / 26214400.0);
        out[26214401] = expf(-red[0]);
    }
}

extern "C" void kernel_launch(void* const* d_in, const int* in_sizes, int n_in,
                              void* d_out, int out_size) {
    const float* x   = (const float*)d_in[0];
    const float* emb = (const float*)d_in[1];
    float* out = (float*)d_out;

    vq_normalize<<<MCOD, 256>>>(emb);
    vq_main<<<P1_BLOCKS, 256>>>(x, emb, out);
    vq_main_tail<<<P2_BLOCKS, 128>>>(x, emb, out);
    vq_finalize<<<1, 256>>>(out);
}

// round 15
// speedup vs baseline: 1.1164x; 1.1164x over previous
#include <cuda_runtime.h>
#include <cstdint>

// Problem constants (fixed by setup_inputs: N=64, T=400, D=1024, M=256)
#define NTOK 25600
#define DDIM 1024
#define MCOD 256
#define KC 16
#define XLD 68        // padded row stride for xs tile (bank-conflict mitigation)
#define NCTA 296      // exactly 2 CTAs per SM (148 SMs) -> perfectly balanced
// CTA c: 87 rows for c<144, 86 rows for c>=144  (144*87 + 152*86 = 25600)

// ---------------- device scratch (allocation-free per harness rules) ----------------
__device__ float  g_enorm[MCOD * DDIM];
__device__ float  g_se[MCOD];
__device__ int    g_counts[MCOD];
__device__ double g_loss;

// ---------------------------------------------------------------------------
// emb_norm[m] = emb[m] / (||emb[m]|| + 1e-4);  se[m] = sum(emb_norm[m]^2)
// Replicates reference rounding: fp32 sum -> sqrtf (IEEE) -> +1e-4 -> IEEE div
// Block 0 additionally zeroes the cross-launch accumulators (graph replays).
// ---------------------------------------------------------------------------
__global__ __launch_bounds__(256) void vq_normalize(const float* __restrict__ emb) {
    __shared__ float red[256];
    const int m = blockIdx.x;
    const int t = threadIdx.x;

    if (m == 0) {
        g_counts[t] = 0;
        if (t == 0) g_loss = 0.0;
    }

    float4 v = ((const float4*)(emb + (size_t)m * DDIM))[t];
    red[t] = v.x * v.x + v.y * v.y + v.z * v.z + v.w * v.w;
    __syncthreads();
    for (int s = 128; s > 0; s >>= 1) {
        if (t < s) red[t] += red[t + s];
        __syncthreads();
    }
    float denom = __fadd_rn(sqrtf(red[0]), 1e-4f);
    __syncthreads();

    float4 e;
    e.x = __fdiv_rn(v.x, denom);
    e.y = __fdiv_rn(v.y, denom);
    e.z = __fdiv_rn(v.z, denom);
    e.w = __fdiv_rn(v.w, denom);
    ((float4*)(g_enorm + (size_t)m * DDIM))[t] = e;

    red[t] = e.x * e.x + e.y * e.y + e.z * e.z + e.w * e.w;
    __syncthreads();
    for (int s = 128; s > 0; s >>= 1) {
        if (t < s) red[t] += red[t + s];
        __syncthreads();
    }
    if (t == 0) g_se[m] = red[0];
}

// ---------------------------------------------------------------------------
// Process one sub-tile of up to 64 rows x all 256 codes: GEMM + argmin +
// counts + gather + straight-through output; commitment-loss partial is
// accumulated into lloss.  Identical per-(row,code) FMA order / rounding /
// tiebreak to the round-12 kernel -> bitwise-identical results.
// Warps whose entire 8-row span is >= nrows skip the FMA loop (dead work).
// ---------------------------------------------------------------------------
__device__ __forceinline__ void process_tile(
    const float* __restrict__ x, const float* __restrict__ emb,
    float* __restrict__ out, size_t rowBase, int nrows,
    float (*xs)[XLD], float (*es)[MCOD], float* ssx, int* sidx,
    int t, float& lloss)
{
    const int ty  = t >> 4;
    const int tx2 = t & 15;

    float acc[4][16];
#pragma unroll
    for (int i = 0; i < 4; i++)
#pragma unroll
        for (int j = 0; j < 16; j++) acc[i][j] = 0.f;

    const int lr = t >> 2;
    const int lq = t & 3;
    const bool xload = (lr < nrows);
    const float* xld = x + (rowBase + (xload ? lr : 0)) * DDIM + lq * 4;
    const float* eld = g_enorm + (size_t)t * DDIM;
    const bool live = (((t >> 5) * 8) < nrows);   // warp covers rows 8w..8w+7
    float sxp = 0.f;

    for (int k0 = 0; k0 < DDIM; k0 += KC) {
        if (xload) {
            float4 xv = *(const float4*)(xld + k0);
            sxp = __fmaf_rn(xv.x, xv.x, sxp);
            sxp = __fmaf_rn(xv.y, xv.y, sxp);
            sxp = __fmaf_rn(xv.z, xv.z, sxp);
            sxp = __fmaf_rn(xv.w, xv.w, sxp);
            xs[lq * 4 + 0][lr] = xv.x;
            xs[lq * 4 + 1][lr] = xv.y;
            xs[lq * 4 + 2][lr] = xv.z;
            xs[lq * 4 + 3][lr] = xv.w;
        }
#pragma unroll
        for (int q = 0; q < 4; q++) {
            float4 ev = *(const float4*)(eld + k0 + q * 4);
            es[q * 4 + 0][t] = ev.x;
            es[q * 4 + 1][t] = ev.y;
            es[q * 4 + 2][t] = ev.z;
            es[q * 4 + 3][t] = ev.w;
        }
        __syncthreads();

        if (live) {
#pragma unroll
            for (int k = 0; k < KC; k++) {
                float4 xr4 = *(const float4*)&xs[k][ty * 4];
                float xr[4] = {xr4.x, xr4.y, xr4.z, xr4.w};
#pragma unroll
                for (int g = 0; g < 4; g++) {
                    float4 er4 = *(const float4*)&es[k][g * 64 + tx2 * 4];
                    float er[4] = {er4.x, er4.y, er4.z, er4.w};
#pragma unroll
                    for (int i = 0; i < 4; i++)
#pragma unroll
                        for (int j = 0; j < 4; j++)
                            acc[i][g * 4 + j] =
                                __fmaf_rn(xr[i], er[j], acc[i][g * 4 + j]);
                }
            }
        }
        __syncthreads();
    }

    // Combine the 4 quad-partials of sum(x^2) for row lr.
    sxp += __shfl_xor_sync(0xffffffffu, sxp, 1);
    sxp += __shfl_xor_sync(0xffffffffu, sxp, 2);
    if (lq == 0) ssx[lr] = sxp;
    __syncthreads();

    const float sx[4] = {ssx[ty * 4 + 0], ssx[ty * 4 + 1],
                         ssx[ty * 4 + 2], ssx[ty * 4 + 3]};

    // Per-thread argmin (reference rounding; lowest index wins ties).
    float bestD[4] = {3.4e38f, 3.4e38f, 3.4e38f, 3.4e38f};
    int   bestI[4] = {0, 0, 0, 0};
#pragma unroll
    for (int g = 0; g < 4; g++) {
#pragma unroll
        for (int j = 0; j < 4; j++) {
            const int cod = g * 64 + tx2 * 4 + j;
            const float sev = g_se[cod];
#pragma unroll
            for (int i = 0; i < 4; i++) {
                float d = __fsub_rn(__fadd_rn(sev, sx[i]),
                                    __fmul_rn(2.0f, acc[i][g * 4 + j]));
                if (d < bestD[i] || (d == bestD[i] && cod < bestI[i])) {
                    bestD[i] = d;
                    bestI[i] = cod;
                }
            }
        }
    }

#pragma unroll
    for (int i = 0; i < 4; i++) {
        float d = bestD[i];
        int   bi = bestI[i];
        for (int off = 8; off > 0; off >>= 1) {
            float od = __shfl_down_sync(0xffffffffu, d, off, 16);
            int   oi = __shfl_down_sync(0xffffffffu, bi, off, 16);
            if (od < d || (od == d && oi < bi)) { d = od; bi = oi; }
        }
        if (tx2 == 0) sidx[ty * 4 + i] = bi;
    }
    __syncthreads();

    if (t < nrows) atomicAdd(&g_counts[sidx[t]], 1);

    // Gather + straight-through output + loss (reference rounding).
    for (int r = 0; r < nrows; ++r) {
        const int idx = sidx[r];
        float4 q  = ((const float4*)(emb + (size_t)idx * DDIM))[t];
        float4 xv = ((const float4*)(x + (rowBase + r) * DDIM))[t];
        float4 o;
        {
            float st = __fadd_rn(xv.x, __fsub_rn(q.x, xv.x));
            o.x = __fmul_rn(__fadd_rn(st, q.x), 0.5f);
            float dd = __fsub_rn(xv.x, q.x);
            lloss = __fmaf_rn(dd, dd, lloss);
        }
        {
            float st = __fadd_rn(xv.y, __fsub_rn(q.y, xv.y));
            o.y = __fmul_rn(__fadd_rn(st, q.y), 0.5f);
            float dd = __fsub_rn(xv.y, q.y);
            lloss = __fmaf_rn(dd, dd, lloss);
        }
        {
            float st = __fadd_rn(xv.z, __fsub_rn(q.z, xv.z));
            o.z = __fmul_rn(__fadd_rn(st, q.z), 0.5f);
            float dd = __fsub_rn(xv.z, q.z);
            lloss = __fmaf_rn(dd, dd, lloss);
        }
        {
            float st = __fadd_rn(xv.w, __fsub_rn(q.w, xv.w));
            o.w = __fmul_rn(__fadd_rn(st, q.w), 0.5f);
            float dd = __fsub_rn(xv.w, q.w);
            lloss = __fmaf_rn(dd, dd, lloss);
        }
        ((float4*)out)[(rowBase + r) * (DDIM / 4) + t] = o;
    }
    __syncthreads();   // sidx/ssx safe for reuse by the next sub-tile
}

// ---------------------------------------------------------------------------
// Main kernel: 296 CTAs (exactly 2/SM), CTA c owns 87 rows (c<144) or 86.
// Each CTA = one full 64-row sub-tile + one 22/23-row sub-tile (dead warps
// skip FMA).  Per-SM work = 2 x ~88 row-units vs round-12's 3 x 64.
// ---------------------------------------------------------------------------
__global__ __launch_bounds__(256, 2) void vq_main(const float* __restrict__ x,
                                                  const float* __restrict__ emb,
                                                  float* __restrict__ out) {
    __shared__ __align__(16) float xs[KC][XLD];
    __shared__ __align__(16) float es[KC][MCOD];
    __shared__ float ssx[64];
    __shared__ int   sidx[64];
    __shared__ float sred[256];

    const int c = blockIdx.x;
    const int t = threadIdx.x;
    const int R = (c < 144) ? 87 : 86;
    const size_t start = (c < 144) ? (size_t)87 * c : (size_t)86 * c + 144;

    float lloss = 0.f;
    process_tile(x, emb, out, start, 64, xs, es, ssx, sidx, t, lloss);
    process_tile(x, emb, out, start + 64, R - 64, xs, es, ssx, sidx, t, lloss);

    sred[t] = lloss;
    __syncthreads();
    for (int s = 128; s > 0; s >>= 1) {
        if (t < s) sred[t] += sred[t + s];
        __syncthreads();
    }
    if (t == 0) atomicAdd(&g_loss, (double)sred[0]);
}

// ---------------------------------------------------------------------------
// Scalars: commitment_loss = mean((x-q)^2), perplexity = exp(-sum p log(p+1e-10))
// ---------------------------------------------------------------------------
__global__ void vq_finalize(float* __restrict__ out) {
    __shared__ float red[256];
    const int t = threadIdx.x;
    float p = (float)g_counts[t] / 25600.0f;
    float term = __fmul_rn(p, logf(__fadd_rn(p, 1e-10f)));
    red[t] = term;
    __syncthreads();
    for (int s = 128; s > 0; s >>= 1) {
        if (t < s) red[t] += red[t + s];
        __syncthreads();
    }
    if (t == 0) {
        out[26214400] = (float)(g_loss / 26214400.0);
        out[26214401] = expf(-red[0]);
    }
}

extern "C" void kernel_launch(void* const* d_in, const int* in_sizes, int n_in,
                              void* d_out, int out_size) {
    const float* x   = (const float*)d_in[0];
    const float* emb = (const float*)d_in[1];
    float* out = (float*)d_out;

    vq_normalize<<<MCOD, 256>>>(emb);
    vq_main<<<NCTA, 256>>>(x, emb, out);
    vq_finalize<<<1, 256>>>(out);
}